// round 15
// baseline (speedup 1.0000x reference)
#include <cuda_runtime.h>
#include <math.h>
#include <stdint.h>
#include <cuda_bf16.h>

#define N_OBJ  4096
#define H      512
#define IN_DIM 1024
#define G6     3072
#define G5     2560
#define NW     6656
#define NLEV   13
#define BM 128
#define BN 128

// ---------------- scratch ------------------------------------------------------
__device__ float g_px_fw[N_OBJ * H];
__device__ float g_x2_fw[N_OBJ * G6];
__device__ float g_px_bw[N_OBJ * H];
__device__ float g_x2_bw[N_OBJ * G5];
__device__ float g_c_fw[(N_OBJ + 1) * H];
__device__ float g_c_bw[(N_OBJ + 1) * H];
__device__ float g_G[2048 * G6];
__device__ float g_stage[2048 * G5];
__device__ __nv_bfloat16 g_hfw_hi[(N_OBJ + 1) * H];
__device__ __nv_bfloat16 g_hfw_lo[(N_OBJ + 1) * H];
__device__ __nv_bfloat16 g_hbw_hi[(N_OBJ + 1) * H];
__device__ __nv_bfloat16 g_hbw_lo[(N_OBJ + 1) * H];
__device__ __nv_bfloat16 g_Ahi[N_OBJ * IN_DIM];
__device__ __nv_bfloat16 g_Alo[N_OBJ * IN_DIM];
__device__ __nv_bfloat16 g_Whi[NW * IN_DIM];
__device__ __nv_bfloat16 g_Wlo[NW * IN_DIM];
__device__ __nv_bfloat16 g_Wfw_hi[G6 * 1024];
__device__ __nv_bfloat16 g_Wfw_lo[G6 * 1024];
__device__ __nv_bfloat16 g_Wbw_hi[G5 * H];
__device__ __nv_bfloat16 g_Wbw_lo[G5 * H];

__device__ __forceinline__ float sigm(float x) { return 1.0f / (1.0f + expf(-x)); }

__global__ void zero_slots_kernel() {
    int t = threadIdx.x;
    g_c_fw[N_OBJ * H + t] = 0.f;
    g_c_bw[N_OBJ * H + t] = 0.f;
    __nv_bfloat16 z = __float2bfloat16(0.f);
    g_hfw_hi[N_OBJ * H + t] = z; g_hfw_lo[N_OBJ * H + t] = z;
    g_hbw_hi[N_OBJ * H + t] = z; g_hbw_lo[N_OBJ * H + t] = z;
}

// ---------------- bf16 hi/lo split ---------------------------------------------
__device__ __forceinline__ void split4(float4 v, unsigned int& h01, unsigned int& h23,
                                       unsigned int& l01, unsigned int& l23) {
    float f[4] = {v.x, v.y, v.z, v.w};
    __nv_bfloat16 h[4], l[4];
#pragma unroll
    for (int k = 0; k < 4; k++) {
        h[k] = __float2bfloat16(f[k]);
        l[k] = __float2bfloat16(f[k] - __bfloat162float(h[k]));
    }
    h01 = (unsigned int)*(unsigned short*)&h[0] | ((unsigned int)*(unsigned short*)&h[1] << 16);
    h23 = (unsigned int)*(unsigned short*)&h[2] | ((unsigned int)*(unsigned short*)&h[3] << 16);
    l01 = (unsigned int)*(unsigned short*)&l[0] | ((unsigned int)*(unsigned short*)&l[1] << 16);
    l23 = (unsigned int)*(unsigned short*)&l[2] | ((unsigned int)*(unsigned short*)&l[3] << 16);
}

#define SS0 1048576
#define SS1 1179648
#define SS2 1966080
#define SS3 2097152
#define SS4 2752512
#define SS5 3145728
#define SS6 3538944
#define SS7 3866624
__global__ void split_all(const float* __restrict__ A,
                          const float* __restrict__ Wpf, const float* __restrict__ Wxf,
                          const float* __restrict__ Wpb, const float* __restrict__ Wxb,
                          const float* __restrict__ Wl, const float* __restrict__ Wr,
                          const float* __restrict__ Wh, int base) {
    long i = base + (long)blockIdx.x * blockDim.x + threadIdx.x;
    if (i >= SS7) return;
    unsigned int h01, h23, l01, l23;
    if (i < SS0) {
        split4(((const float4*)A)[i], h01, h23, l01, l23);
        ((uint2*)g_Ahi)[i] = make_uint2(h01, h23);
        ((uint2*)g_Alo)[i] = make_uint2(l01, l23);
    } else if (i < SS4) {
        const float* src; long j; long doff;
        if (i < SS1)      { src = Wpf; j = i - SS0; doff = 0; }
        else if (i < SS2) { src = Wxf; j = i - SS1; doff = 131072; }
        else if (i < SS3) { src = Wpb; j = i - SS2; doff = 917504; }
        else              { src = Wxb; j = i - SS3; doff = 1048576; }
        split4(((const float4*)src)[j], h01, h23, l01, l23);
        ((uint2*)g_Whi)[doff + j] = make_uint2(h01, h23);
        ((uint2*)g_Wlo)[doff + j] = make_uint2(l01, l23);
    } else if (i < SS6) {
        const float* src; long j; long coff;
        if (i < SS5) { src = Wl; j = i - SS4; coff = 0; }
        else         { src = Wr; j = i - SS5; coff = 128; }
        split4(((const float4*)src)[j], h01, h23, l01, l23);
        long row = j >> 7, c4 = j & 127;
        long d = row * 256 + coff + c4;
        ((uint2*)g_Wfw_hi)[d] = make_uint2(h01, h23);
        ((uint2*)g_Wfw_lo)[d] = make_uint2(l01, l23);
    } else {
        long j = i - SS6;
        split4(((const float4*)Wh)[j], h01, h23, l01, l23);
        ((uint2*)g_Wbw_hi)[j] = make_uint2(h01, h23);
        ((uint2*)g_Wbw_lo)[j] = make_uint2(l01, l23);
    }
}

// ================= mma.sync machinery ==========================================
#define MMA_BF16(acc, A, b0_, b1_)                                               \
    asm volatile("mma.sync.aligned.m16n8k16.row.col.f32.bf16.bf16.f32 "          \
                 "{%0,%1,%2,%3},{%4,%5,%6,%7},{%8,%9},{%0,%1,%2,%3};"            \
                 : "+f"(acc[0]), "+f"(acc[1]), "+f"(acc[2]), "+f"(acc[3])        \
                 : "r"(A[0]), "r"(A[1]), "r"(A[2]), "r"(A[3]), "r"(b0_), "r"(b1_))

#define LDSM4(r, addr)                                                           \
    asm volatile("ldmatrix.sync.aligned.m8n8.x4.shared.b16 {%0,%1,%2,%3}, [%4];" \
                 : "=r"((r)[0]), "=r"((r)[1]), "=r"((r)[2]), "=r"((r)[3])        \
                 : "r"(addr))

// pipeline geometry: 2 buffers x 4 planes x 128 rows x 80B
#define P2PITCH 80
#define P2PLANE (128 * P2PITCH)
#define P2BUF   (4 * P2PLANE)
#define P2SMEM  (2 * P2BUF)

__device__ __forceinline__ void tc_compute2(unsigned int base, float (&acc)[2][8][4],
                                            unsigned int aoffA2, unsigned int aoffB2) {
#pragma unroll
    for (int ksub = 0; ksub < 2; ksub++) {
        const unsigned int b0a = base + ksub * 32;
        unsigned int ah[2][4], al[2][4];
        LDSM4(ah[0], b0a + aoffA2);
        LDSM4(ah[1], b0a + aoffA2 + 1280);
        LDSM4(al[0], b0a + P2PLANE + aoffA2);
        LDSM4(al[1], b0a + P2PLANE + aoffA2 + 1280);
#pragma unroll
        for (int p = 0; p < 4; p++) {
            unsigned int bh[4], bl[4];
            LDSM4(bh, b0a + 2 * P2PLANE + aoffB2 + p * 1280);
            LDSM4(bl, b0a + 3 * P2PLANE + aoffB2 + p * 1280);
#pragma unroll
            for (int mt = 0; mt < 2; mt++) {
                MMA_BF16(acc[mt][2 * p],     ah[mt], bh[0], bh[1]);
                MMA_BF16(acc[mt][2 * p],     ah[mt], bl[0], bl[1]);
                MMA_BF16(acc[mt][2 * p],     al[mt], bh[0], bh[1]);
                MMA_BF16(acc[mt][2 * p + 1], ah[mt], bh[2], bh[3]);
                MMA_BF16(acc[mt][2 * p + 1], ah[mt], bl[2], bl[3]);
                MMA_BF16(acc[mt][2 * p + 1], al[mt], bh[2], bh[3]);
            }
        }
    }
}

#define FRAG_OFFS                                                                \
    const int tid = threadIdx.x;                                                 \
    const int wid = tid >> 5, lane = tid & 31;                                   \
    const int gid = lane >> 2, tig = lane & 3;                                   \
    const int warpM = wid & 3, warpN = wid >> 2;                                 \
    const unsigned int aoffA2 = (warpM * 32 + (lane & 7) + ((lane >> 3) & 1) * 8) * P2PITCH \
                                + (lane >> 4) * 16;                              \
    const unsigned int aoffB2 = (warpN * 64 + (lane & 7) + (lane >> 4) * 8) * P2PITCH \
                                + ((lane >> 3) & 1) * 16;

// ========== projection (R14 proven) ===========================================
__global__ void __launch_bounds__(256, 2)
proj_tc2(const float* __restrict__ bpf, float* __restrict__ pxf,
         const float* __restrict__ bxf, float* __restrict__ x2f,
         const float* __restrict__ bpb, float* __restrict__ pxb,
         const float* __restrict__ bxb, float* __restrict__ x2b)
{
    extern __shared__ __align__(16) char dynsm[];
    FRAG_OFFS
    const unsigned int sdyn = (unsigned int)__cvta_generic_to_shared(dynsm);

    const int rowBase = blockIdx.y * BM;
    const int cb = blockIdx.x * BN;

    const float* bias; float* C; int segN, lc;
    if (cb < 512)       { bias = bpf; C = pxf; segN = 512; lc = cb; }
    else if (cb < 3584) { bias = bxf; C = x2f; segN = G6;  lc = cb - 512; }
    else if (cb < 4096) { bias = bpb; C = pxb; segN = 512; lc = cb - 3584; }
    else                { bias = bxb; C = x2b; segN = G5;  lc = cb - 4096; }

    const __nv_bfloat16* gptr[8];
    unsigned int smoff[8];
#pragma unroll
    for (int j = 0; j < 8; j++) {
        const int idx = tid + j * 256;
        const int plane = idx >> 9;
        const int rem = idx & 511;
        const int row = rem >> 2;
        const int c16 = rem & 3;
        const __nv_bfloat16* base;
        if (plane == 0)      base = g_Ahi + (size_t)(rowBase + row) * IN_DIM;
        else if (plane == 1) base = g_Alo + (size_t)(rowBase + row) * IN_DIM;
        else if (plane == 2) base = g_Whi + (size_t)(cb + row) * IN_DIM;
        else                 base = g_Wlo + (size_t)(cb + row) * IN_DIM;
        gptr[j] = base + c16 * 8;
        smoff[j] = plane * P2PLANE + row * P2PITCH + c16 * 16;
    }

#define P2LOAD(buf, k0) {                                                        \
    _Pragma("unroll") for (int j = 0; j < 8; j++) {                              \
        unsigned int sa = sdyn + (buf) * P2BUF + smoff[j];                       \
        asm volatile("cp.async.cg.shared.global [%0], [%1], 16;"                 \
                     :: "r"(sa), "l"(gptr[j] + (k0)));                           \
    }                                                                            \
    asm volatile("cp.async.commit_group;"); }

    float acc[2][8][4];
#pragma unroll
    for (int mt = 0; mt < 2; mt++)
#pragma unroll
        for (int nt = 0; nt < 8; nt++)
#pragma unroll
            for (int q = 0; q < 4; q++) acc[mt][nt][q] = 0.f;

    const int NST = IN_DIM / 32;
    P2LOAD(0, 0)
    P2LOAD(1, 32)

    for (int s = 0; s < NST; s++) {
        if (s < NST - 2) { asm volatile("cp.async.wait_group 1;"); }
        else             { asm volatile("cp.async.wait_group 0;"); }
        __syncthreads();
        tc_compute2(sdyn + (s & 1) * P2BUF, acc, aoffA2, aoffB2);
        __syncthreads();
        if (s + 2 < NST) { P2LOAD(s & 1, (s + 2) * 32) }
    }
#undef P2LOAD

#pragma unroll
    for (int mt = 0; mt < 2; mt++) {
#pragma unroll
        for (int nt = 0; nt < 8; nt++) {
            const int col = lc + warpN * 64 + nt * 8 + 2 * tig;
            const float b0 = bias[col], b1 = bias[col + 1];
            const int r0 = rowBase + warpM * 32 + mt * 16 + gid;
            float* c0 = C + (size_t)r0 * segN + col;
            c0[0] = acc[mt][nt][0] + b0;
            c0[1] = acc[mt][nt][1] + b1;
            float* c1 = C + (size_t)(r0 + 8) * segN + col;
            c1[0] = acc[mt][nt][2] + b0;
            c1[1] = acc[mt][nt][3] + b1;
        }
    }
}

// ====== MEGA level GEMM v2: cp.async pipeline, K-stage 32 =====================
__global__ void __launch_bounds__(256, 2)
mega_tc2(const int* __restrict__ lch, const int* __restrict__ rch,
         float* __restrict__ Gp, int sF, int mgF, int ksF, int rowsF, int tilesF,
         float* __restrict__ stage, int sB, int mgB, int ksB, int rowsB)
{
    extern __shared__ __align__(16) char dynsm[];
    FRAG_OFFS
    const unsigned int sdyn = (unsigned int)__cvta_generic_to_shared(dynsm);

    int bx = blockIdx.x;
    const bool isF = bx < tilesF;
    if (!isF) bx -= tilesF;
    const int colTiles = isF ? 24 : 20;
    const int rows = isF ? rowsF : rowsB;
    const int colBase = (bx % colTiles) * BN;
    const int rowBase = ((bx / colTiles) % rows) * BM;
    const int z = bx / (colTiles * rows);
    const int mg = isF ? mgF : mgB;
    const int KTOT = isF ? 1024 : 512;
    const int ks = isF ? ksF : ksB;
    const int chunk = KTOT / ks;
    const int kBase = z * chunk;

    // per-thread cp.async descriptors (8 x 16B per stage)
    const __nv_bfloat16 *gp0[8], *gp1[4];
    unsigned int smoff[8];
#pragma unroll
    for (int j = 0; j < 8; j++) {
        const int idx = tid + j * 256;
        const int plane = idx >> 9;
        const int rem = idx & 511;
        const int row = rem >> 2;
        const int c16 = rem & 3;
        if (plane < 2) {
            int r = rowBase + row; if (r >= mg) r = mg - 1;
            if (isF) {
                const int node = sF + r;
                const int il = lch[node], ir = rch[node];
                const __nv_bfloat16* hiB = plane ? g_hfw_lo : g_hfw_hi;
                gp0[j] = hiB + (size_t)il * H + c16 * 8;
                gp1[j] = hiB + (size_t)ir * H - H + c16 * 8;
            } else {
                const int node = sB + r;
                const __nv_bfloat16* hiB = plane ? g_hbw_lo : g_hbw_hi;
                gp0[j] = hiB + (size_t)node * H + c16 * 8;
                gp1[j] = gp0[j];
            }
        } else {
            const __nv_bfloat16* wB;
            if (isF) wB = (plane == 2) ? g_Wfw_hi : g_Wfw_lo;
            else     wB = (plane == 2) ? g_Wbw_hi : g_Wbw_lo;
            gp0[j] = wB + (size_t)(colBase + row) * KTOT + c16 * 8;
        }
        smoff[j] = plane * P2PLANE + row * P2PITCH + c16 * 16;
    }

#define MLOAD(buf, k0) {                                                          \
    const bool hiHalf = isF && ((k0) >= H);                                       \
    _Pragma("unroll") for (int j = 0; j < 8; j++) {                               \
        const __nv_bfloat16* src = (j < 4 && hiHalf) ? gp1[j] : gp0[j];           \
        unsigned int sa = sdyn + (buf) * P2BUF + smoff[j];                        \
        asm volatile("cp.async.cg.shared.global [%0], [%1], 16;"                  \
                     :: "r"(sa), "l"(src + (k0)));                                \
    }                                                                             \
    asm volatile("cp.async.commit_group;"); }

    float acc[2][8][4];
#pragma unroll
    for (int mt = 0; mt < 2; mt++)
#pragma unroll
        for (int nt = 0; nt < 8; nt++)
#pragma unroll
            for (int q = 0; q < 4; q++) acc[mt][nt][q] = 0.f;

    const int NST = chunk / 32;
    MLOAD(0, kBase)
    if (NST > 1) { MLOAD(1, kBase + 32) }

    for (int s = 0; s < NST; s++) {
        if (s < NST - 2) { asm volatile("cp.async.wait_group 1;"); }
        else             { asm volatile("cp.async.wait_group 0;"); }
        __syncthreads();
        tc_compute2(sdyn + (s & 1) * P2BUF, acc, aoffA2, aoffB2);
        __syncthreads();
        if (s + 2 < NST) { MLOAD(s & 1, kBase + (s + 2) * 32) }
    }
#undef MLOAD

    float* outp = isF ? Gp : stage;
    const int stride = isF ? G6 : G5;
#pragma unroll
    for (int mt = 0; mt < 2; mt++) {
#pragma unroll
        for (int nt = 0; nt < 8; nt++) {
            const int col = colBase + warpN * 64 + nt * 8 + 2 * tig;
            const int ro = rowBase + warpM * 32 + mt * 16 + gid;
            if (ro < mg) {
                float* p = outp + (size_t)(z * mg + ro) * stride + col;
                p[0] = acc[mt][nt][0]; p[1] = acc[mt][nt][1];
            }
            if (ro + 8 < mg) {
                float* p = outp + (size_t)(z * mg + ro + 8) * stride + col;
                p[0] = acc[mt][nt][2]; p[1] = acc[mt][nt][3];
            }
        }
    }
}

// ====== MEGA gates (writeA: emit layer-2 proj input splits directly) =========
__global__ void gates_mega(
    const float* __restrict__ Gp, const float* __restrict__ x2f,
    const float* __restrict__ pxf,
    const float* __restrict__ bl, const float* __restrict__ br,
    float* __restrict__ cbf,
    const int* __restrict__ lch, const int* __restrict__ rch,
    int sF, int mF, int mgF, int ksF,
    const float* __restrict__ stage, const float* __restrict__ x2b,
    const float* __restrict__ pxb, const float* __restrict__ bh,
    float* __restrict__ cbb,
    const int* __restrict__ par, int sB, int sPar, int mPar, int ksPar,
    float* __restrict__ dst, int writeA)
{
    const int col = threadIdx.x;
    int j = blockIdx.x;
    if (j < mF) {
        const int node = sF + j;
        float v[6];
        const float* xr = x2f + (size_t)node * G6;
#pragma unroll
        for (int g = 0; g < 6; g++) v[g] = xr[g * H + col] + bl[g * H + col] + br[g * H + col];
        if (j < mgF) {
            for (int z = 0; z < ksF; z++) {
                const float* gp = Gp + (size_t)(z * mgF + j) * G6;
#pragma unroll
                for (int g = 0; g < 6; g++) v[g] += gp[g * H + col];
            }
        }
        float iv = sigm(v[0]), ov = sigm(v[1]), fl = sigm(v[2]), fr = sigm(v[3]);
        float uv = tanhf(v[4]), rv = sigm(v[5]);
        float cl = cbf[(size_t)lch[node] * H + col];
        float cr = cbf[(size_t)rch[node] * H + col];
        float c = iv * uv + fl * cl + fr * cr;
        float hc = ov * tanhf(c);
        float hf = rv * hc + (1.f - rv) * pxf[(size_t)node * H + col];
        cbf[(size_t)node * H + col] = c;
        __nv_bfloat16 hh = __float2bfloat16(hf);
        __nv_bfloat16 ll = __float2bfloat16(hf - __bfloat162float(hh));
        g_hfw_hi[(size_t)node * H + col] = hh;
        g_hfw_lo[(size_t)node * H + col] = ll;
        if (writeA) {
            g_Ahi[(size_t)node * IN_DIM + col] = hh;
            g_Alo[(size_t)node * IN_DIM + col] = ll;
        } else {
            dst[(size_t)node * IN_DIM + col] = hf;
        }
    } else {
        j -= mF;
        const int node = sB + j;
        const float* xr = x2b + (size_t)node * G5;
        float v[5];
#pragma unroll
        for (int g = 0; g < 5; g++) v[g] = xr[g * H + col] + bh[g * H + col];
        if (sPar >= 0) {
            const int rp = par[node] - sPar;
            for (int z = 0; z < ksPar; z++) {
                const float* y = stage + (size_t)(z * mPar + rp) * G5;
#pragma unroll
                for (int g = 0; g < 5; g++) v[g] += y[g * H + col];
            }
        }
        float iv = sigm(v[0]), ov = sigm(v[1]), fv = sigm(v[2]);
        float uv = tanhf(v[3]), rv = sigm(v[4]);
        float cp = cbb[(size_t)par[node] * H + col];
        float c = iv * uv + fv * cp;
        float hc = ov * tanhf(c);
        float hf = rv * hc + (1.f - rv) * pxb[(size_t)node * H + col];
        cbb[(size_t)node * H + col] = c;
        __nv_bfloat16 hh = __float2bfloat16(hf);
        __nv_bfloat16 ll = __float2bfloat16(hf - __bfloat162float(hh));
        g_hbw_hi[(size_t)node * H + col] = hh;
        g_hbw_lo[(size_t)node * H + col] = ll;
        if (writeA) {
            g_Ahi[(size_t)node * IN_DIM + H + col] = hh;
            g_Alo[(size_t)node * IN_DIM + H + col] = ll;
        } else {
            dst[(size_t)node * IN_DIM + H + col] = hf;
        }
    }
}

static inline int ksel(int mg) {
    if (mg <= 32)  return 16;
    if (mg <= 128) return 8;
    if (mg <= 512) return 4;
    return 2;
}

// ------------------------------- launch ---------------------------------------
extern "C" void kernel_launch(void* const* d_in, const int* in_sizes, int n_in,
                              void* d_out, int out_size) {
    const float* features = (const float*)d_in[0];
    const float* fw_Wp = (const float*)d_in[1];
    const float* fw_bp = (const float*)d_in[2];
    const float* fw_Wx = (const float*)d_in[3];
    const float* fw_bx = (const float*)d_in[4];
    const float* fw_Wl = (const float*)d_in[5];
    const float* fw_bl = (const float*)d_in[6];
    const float* fw_Wr = (const float*)d_in[7];
    const float* fw_br = (const float*)d_in[8];
    const float* bw_Wp = (const float*)d_in[9];
    const float* bw_bp = (const float*)d_in[10];
    const float* bw_Wx = (const float*)d_in[11];
    const float* bw_bx = (const float*)d_in[12];
    const float* bw_Wh = (const float*)d_in[13];
    const float* bw_bh = (const float*)d_in[14];
    const int* left   = (const int*)d_in[17];
    const int* right  = (const int*)d_in[18];
    const int* parent = (const int*)d_in[19];
    float* out = (float*)d_out;

    float *px_fw, *x2_fw, *px_bw, *x2_bw, *c_fw, *c_bw, *Gs, *stg;
    cudaGetSymbolAddress((void**)&px_fw, g_px_fw);
    cudaGetSymbolAddress((void**)&x2_fw, g_x2_fw);
    cudaGetSymbolAddress((void**)&px_bw, g_px_bw);
    cudaGetSymbolAddress((void**)&x2_bw, g_x2_bw);
    cudaGetSymbolAddress((void**)&c_fw, g_c_fw);
    cudaGetSymbolAddress((void**)&c_bw, g_c_bw);
    cudaGetSymbolAddress((void**)&Gs, g_G);
    cudaGetSymbolAddress((void**)&stg, g_stage);

    cudaFuncSetAttribute(proj_tc2, cudaFuncAttributeMaxDynamicSharedMemorySize, P2SMEM);
    cudaFuncSetAttribute(mega_tc2, cudaFuncAttributeMaxDynamicSharedMemorySize, P2SMEM);

    zero_slots_kernel<<<1, H>>>();

    static const int LSTART[NLEV] = {0, 1, 3, 7, 15, 31, 63, 127, 255, 511, 1023, 2047, 4095};
    static const int LSIZE[NLEV]  = {1, 2, 4, 8, 16, 32, 64, 128, 256, 512, 1024, 2048, 1};
    static const int MGV[NLEV]    = {1, 2, 4, 8, 16, 32, 64, 128, 256, 512, 1024, 1, 0};

    for (int l = 0; l < 2; l++) {
        const float* Wp_f = fw_Wp + (size_t)l * H * IN_DIM;
        const float* bp_f = fw_bp + (size_t)l * H;
        const float* Wx_f = fw_Wx + (size_t)l * G6 * IN_DIM;
        const float* bx_f = fw_bx + (size_t)l * G6;
        const float* Wl_  = fw_Wl + (size_t)l * G6 * H;
        const float* bl_  = fw_bl + (size_t)l * G6;
        const float* Wr_  = fw_Wr + (size_t)l * G6 * H;
        const float* br_  = fw_br + (size_t)l * G6;
        const float* Wp_b = bw_Wp + (size_t)l * H * IN_DIM;
        const float* bp_b = bw_bp + (size_t)l * H;
        const float* Wx_b = bw_Wx + (size_t)l * G5 * IN_DIM;
        const float* bx_b = bw_bx + (size_t)l * G5;
        const float* Wh_  = bw_Wh + (size_t)l * G5 * H;
        const float* bh_  = bw_bh + (size_t)l * G5;

        // layer 0: split A + all weights. layer 1: A comes pre-split from gates.
        const int base = (l == 0) ? 0 : SS0;
        split_all<<<(SS7 - base + 255) / 256, 256>>>(features, Wp_f, Wx_f, Wp_b, Wx_b,
                                                     Wl_, Wr_, Wh_, base);

        proj_tc2<<<dim3(NW / BN, N_OBJ / BM), 256, P2SMEM>>>(
            bp_f, px_fw, bx_f, x2_fw, bp_b, px_bw, bx_b, x2_bw);

        for (int t = 0; t < NLEV; t++) {
            const int dF = NLEV - 1 - t;
            const int sF = LSTART[dF], mF = LSIZE[dF], mgF = MGV[dF];
            const int ksF = ksel(mgF > 0 ? mgF : 1);
            const int rowsF = (mgF + BM - 1) / BM;
            const int tilesF = (mgF > 0) ? 24 * rowsF * ksF : 0;

            const int sB = LSTART[t], mB = LSIZE[t];
            const int dY = t - 1;
            const int mgB = (t >= 1) ? MGV[dY] : 0;
            const int ksB = ksel(mgB > 0 ? mgB : 1);
            const int rowsB = (mgB + BM - 1) / BM;
            const int tilesB = (mgB > 0) ? 20 * rowsB * ksB : 0;

            if (tilesF + tilesB > 0)
                mega_tc2<<<tilesF + tilesB, 256, P2SMEM>>>(
                    left, right, Gs, sF, (mgF > 0 ? mgF : 1), ksF,
                    (rowsF > 0 ? rowsF : 1), tilesF,
                    stg, LSTART[dY >= 0 ? dY : 0], (mgB > 0 ? mgB : 1),
                    ksB, (rowsB > 0 ? rowsB : 1));

            gates_mega<<<mF + mB, H>>>(
                Gs, x2_fw, px_fw, bl_, br_, c_fw, left, right,
                sF, mF, mgF, ksF,
                stg, x2_bw, px_bw, bh_, c_bw, parent,
                sB, (t >= 1) ? LSTART[dY] : -1, (mgB > 0 ? mgB : 1), ksB,
                out, (l == 0) ? 1 : 0);
        }
    }
}

// round 16
// speedup vs baseline: 1.1122x; 1.1122x over previous
#include <cuda_runtime.h>
#include <math.h>
#include <stdint.h>
#include <cuda_bf16.h>

#define N_OBJ  4096
#define H      512
#define IN_DIM 1024
#define G6     3072
#define G5     2560
#define NW     6656
#define NLEV   13
#define BM 128
#define BN 128
#define SPITCH 24

// ---------------- scratch ------------------------------------------------------
__device__ float g_px_fw[N_OBJ * H];
__device__ float g_x2_fw[N_OBJ * G6];
__device__ float g_px_bw[N_OBJ * H];
__device__ float g_x2_bw[N_OBJ * G5];
__device__ float g_c_fw[(N_OBJ + 1) * H];
__device__ float g_c_bw[(N_OBJ + 1) * H];
__device__ float g_G[2048 * G6];
__device__ float g_stage[2048 * G5];
__device__ __nv_bfloat16 g_hfw_hi[(N_OBJ + 1) * H];
__device__ __nv_bfloat16 g_hfw_lo[(N_OBJ + 1) * H];
__device__ __nv_bfloat16 g_hbw_hi[(N_OBJ + 1) * H];
__device__ __nv_bfloat16 g_hbw_lo[(N_OBJ + 1) * H];
__device__ __nv_bfloat16 g_Ahi[N_OBJ * IN_DIM];
__device__ __nv_bfloat16 g_Alo[N_OBJ * IN_DIM];
__device__ __nv_bfloat16 g_Whi[NW * IN_DIM];
__device__ __nv_bfloat16 g_Wlo[NW * IN_DIM];
__device__ __nv_bfloat16 g_Wfw_hi[G6 * 1024];
__device__ __nv_bfloat16 g_Wfw_lo[G6 * 1024];
__device__ __nv_bfloat16 g_Wbw_hi[G5 * H];
__device__ __nv_bfloat16 g_Wbw_lo[G5 * H];

__device__ __forceinline__ float sigm(float x) { return 1.0f / (1.0f + expf(-x)); }

__global__ void zero_slots_kernel() {
    int t = threadIdx.x;
    g_c_fw[N_OBJ * H + t] = 0.f;
    g_c_bw[N_OBJ * H + t] = 0.f;
    __nv_bfloat16 z = __float2bfloat16(0.f);
    g_hfw_hi[N_OBJ * H + t] = z; g_hfw_lo[N_OBJ * H + t] = z;
    g_hbw_hi[N_OBJ * H + t] = z; g_hbw_lo[N_OBJ * H + t] = z;
}

// ---------------- bf16 hi/lo split ---------------------------------------------
__device__ __forceinline__ void split4(float4 v, unsigned int& h01, unsigned int& h23,
                                       unsigned int& l01, unsigned int& l23) {
    float f[4] = {v.x, v.y, v.z, v.w};
    __nv_bfloat16 h[4], l[4];
#pragma unroll
    for (int k = 0; k < 4; k++) {
        h[k] = __float2bfloat16(f[k]);
        l[k] = __float2bfloat16(f[k] - __bfloat162float(h[k]));
    }
    h01 = (unsigned int)*(unsigned short*)&h[0] | ((unsigned int)*(unsigned short*)&h[1] << 16);
    h23 = (unsigned int)*(unsigned short*)&h[2] | ((unsigned int)*(unsigned short*)&h[3] << 16);
    l01 = (unsigned int)*(unsigned short*)&l[0] | ((unsigned int)*(unsigned short*)&l[1] << 16);
    l23 = (unsigned int)*(unsigned short*)&l[2] | ((unsigned int)*(unsigned short*)&l[3] << 16);
}

#define SS0 1048576
#define SS1 1179648
#define SS2 1966080
#define SS3 2097152
#define SS4 2752512
#define SS5 3145728
#define SS6 3538944
#define SS7 3866624
__global__ void split_all(const float* __restrict__ A,
                          const float* __restrict__ Wpf, const float* __restrict__ Wxf,
                          const float* __restrict__ Wpb, const float* __restrict__ Wxb,
                          const float* __restrict__ Wl, const float* __restrict__ Wr,
                          const float* __restrict__ Wh, int base) {
    long i = base + (long)blockIdx.x * blockDim.x + threadIdx.x;
    if (i >= SS7) return;
    unsigned int h01, h23, l01, l23;
    if (i < SS0) {
        split4(((const float4*)A)[i], h01, h23, l01, l23);
        ((uint2*)g_Ahi)[i] = make_uint2(h01, h23);
        ((uint2*)g_Alo)[i] = make_uint2(l01, l23);
    } else if (i < SS4) {
        const float* src; long j; long doff;
        if (i < SS1)      { src = Wpf; j = i - SS0; doff = 0; }
        else if (i < SS2) { src = Wxf; j = i - SS1; doff = 131072; }
        else if (i < SS3) { src = Wpb; j = i - SS2; doff = 917504; }
        else              { src = Wxb; j = i - SS3; doff = 1048576; }
        split4(((const float4*)src)[j], h01, h23, l01, l23);
        ((uint2*)g_Whi)[doff + j] = make_uint2(h01, h23);
        ((uint2*)g_Wlo)[doff + j] = make_uint2(l01, l23);
    } else if (i < SS6) {
        const float* src; long j; long coff;
        if (i < SS5) { src = Wl; j = i - SS4; coff = 0; }
        else         { src = Wr; j = i - SS5; coff = 128; }
        split4(((const float4*)src)[j], h01, h23, l01, l23);
        long row = j >> 7, c4 = j & 127;
        long d = row * 256 + coff + c4;
        ((uint2*)g_Wfw_hi)[d] = make_uint2(h01, h23);
        ((uint2*)g_Wfw_lo)[d] = make_uint2(l01, l23);
    } else {
        long j = i - SS6;
        split4(((const float4*)Wh)[j], h01, h23, l01, l23);
        ((uint2*)g_Wbw_hi)[j] = make_uint2(h01, h23);
        ((uint2*)g_Wbw_lo)[j] = make_uint2(l01, l23);
    }
}

// ================= mma.sync machinery ==========================================
#define MMA_BF16(acc, A, b0_, b1_)                                               \
    asm volatile("mma.sync.aligned.m16n8k16.row.col.f32.bf16.bf16.f32 "          \
                 "{%0,%1,%2,%3},{%4,%5,%6,%7},{%8,%9},{%0,%1,%2,%3};"            \
                 : "+f"(acc[0]), "+f"(acc[1]), "+f"(acc[2]), "+f"(acc[3])        \
                 : "r"(A[0]), "r"(A[1]), "r"(A[2]), "r"(A[3]), "r"(b0_), "r"(b1_))

#define LDSM4(r, addr)                                                           \
    asm volatile("ldmatrix.sync.aligned.m8n8.x4.shared.b16 {%0,%1,%2,%3}, [%4];" \
                 : "=r"((r)[0]), "=r"((r)[1]), "=r"((r)[2]), "=r"((r)[3])        \
                 : "r"(addr))

#define PLANE_B  (128 * SPITCH * 2)
#define BUF_B    (4 * PLANE_B)

#define TC_COMPUTE_LDSM(buf)                                                     \
    {                                                                            \
        const unsigned int b0a = smem_u32 + (buf) * BUF_B;                       \
        unsigned int ah[2][4], al[2][4];                                         \
        LDSM4(ah[0], b0a + aoffA);                                               \
        LDSM4(ah[1], b0a + aoffA + 768);                                         \
        LDSM4(al[0], b0a + PLANE_B + aoffA);                                     \
        LDSM4(al[1], b0a + PLANE_B + aoffA + 768);                               \
        _Pragma("unroll") for (int p = 0; p < 4; p++) {                          \
            unsigned int bh[4], bl[4];                                           \
            LDSM4(bh, b0a + 2 * PLANE_B + aoffB + p * 768);                      \
            LDSM4(bl, b0a + 3 * PLANE_B + aoffB + p * 768);                      \
            _Pragma("unroll") for (int mt = 0; mt < 2; mt++) {                   \
                MMA_BF16(acc[mt][2 * p],     ah[mt], bh[0], bh[1]);              \
                MMA_BF16(acc[mt][2 * p],     ah[mt], bl[0], bl[1]);              \
                MMA_BF16(acc[mt][2 * p],     al[mt], bh[0], bh[1]);              \
                MMA_BF16(acc[mt][2 * p + 1], ah[mt], bh[2], bh[3]);              \
                MMA_BF16(acc[mt][2 * p + 1], ah[mt], bl[2], bl[3]);              \
                MMA_BF16(acc[mt][2 * p + 1], al[mt], bh[2], bh[3]);              \
            }                                                                    \
        }                                                                        \
    }

#define TC_PROLOG                                                                \
    const int tid = threadIdx.x;                                                 \
    const int wid = tid >> 5, lane = tid & 31;                                   \
    const int gid = lane >> 2, tig = lane & 3;                                   \
    const int warpM = wid & 3, warpN = wid >> 2;                                 \
    const unsigned int smem_u32 = (unsigned int)__cvta_generic_to_shared(&sm[0][0][0]); \
    const unsigned int aoffA = ((warpM * 32 + (lane & 7) + ((lane >> 3) & 1) * 8) * SPITCH \
                                + (lane >> 4) * 8) * 2;                          \
    const unsigned int aoffB = ((warpN * 64 + (lane & 7) + (lane >> 4) * 8) * SPITCH \
                                + ((lane >> 3) & 1) * 8) * 2;

#define SM_STORE(b)                                                    \
    *(uint4*)&sm[b][0][smOff] = rAh;                                   \
    *(uint4*)&sm[b][1][smOff] = rAl;                                   \
    *(uint4*)&sm[b][2][smOff] = rBh;                                   \
    *(uint4*)&sm[b][3][smOff] = rBl;

// ========== projection v2: cp.async pipeline, K-stage 32 (R14 proven) =========
#define P2PITCH 80
#define P2PLANE (128 * P2PITCH)
#define P2BUF   (4 * P2PLANE)
#define P2SMEM  (2 * P2BUF)

__device__ __forceinline__ void tc_compute2(unsigned int base, float (&acc)[2][8][4],
                                            unsigned int aoffA2, unsigned int aoffB2) {
#pragma unroll
    for (int ksub = 0; ksub < 2; ksub++) {
        const unsigned int b0a = base + ksub * 32;
        unsigned int ah[2][4], al[2][4];
        LDSM4(ah[0], b0a + aoffA2);
        LDSM4(ah[1], b0a + aoffA2 + 1280);
        LDSM4(al[0], b0a + P2PLANE + aoffA2);
        LDSM4(al[1], b0a + P2PLANE + aoffA2 + 1280);
#pragma unroll
        for (int p = 0; p < 4; p++) {
            unsigned int bh[4], bl[4];
            LDSM4(bh, b0a + 2 * P2PLANE + aoffB2 + p * 1280);
            LDSM4(bl, b0a + 3 * P2PLANE + aoffB2 + p * 1280);
#pragma unroll
            for (int mt = 0; mt < 2; mt++) {
                MMA_BF16(acc[mt][2 * p],     ah[mt], bh[0], bh[1]);
                MMA_BF16(acc[mt][2 * p],     ah[mt], bl[0], bl[1]);
                MMA_BF16(acc[mt][2 * p],     al[mt], bh[0], bh[1]);
                MMA_BF16(acc[mt][2 * p + 1], ah[mt], bh[2], bh[3]);
                MMA_BF16(acc[mt][2 * p + 1], ah[mt], bl[2], bl[3]);
                MMA_BF16(acc[mt][2 * p + 1], al[mt], bh[2], bh[3]);
            }
        }
    }
}

__global__ void __launch_bounds__(256, 2)
proj_tc2(const float* __restrict__ bpf, float* __restrict__ pxf,
         const float* __restrict__ bxf, float* __restrict__ x2f,
         const float* __restrict__ bpb, float* __restrict__ pxb,
         const float* __restrict__ bxb, float* __restrict__ x2b)
{
    extern __shared__ __align__(16) char dynsm[];
    const int tid = threadIdx.x;
    const int wid = tid >> 5, lane = tid & 31;
    const int gid = lane >> 2, tig = lane & 3;
    const int warpM = wid & 3, warpN = wid >> 2;
    const unsigned int sdyn = (unsigned int)__cvta_generic_to_shared(dynsm);
    const unsigned int aoffA2 = (warpM * 32 + (lane & 7) + ((lane >> 3) & 1) * 8) * P2PITCH
                                + (lane >> 4) * 16;
    const unsigned int aoffB2 = (warpN * 64 + (lane & 7) + (lane >> 4) * 8) * P2PITCH
                                + ((lane >> 3) & 1) * 16;

    const int rowBase = blockIdx.y * BM;
    const int cb = blockIdx.x * BN;

    const float* bias; float* C; int segN, lc;
    if (cb < 512)       { bias = bpf; C = pxf; segN = 512; lc = cb; }
    else if (cb < 3584) { bias = bxf; C = x2f; segN = G6;  lc = cb - 512; }
    else if (cb < 4096) { bias = bpb; C = pxb; segN = 512; lc = cb - 3584; }
    else                { bias = bxb; C = x2b; segN = G5;  lc = cb - 4096; }

    const __nv_bfloat16* gptr[8];
    unsigned int smoff[8];
#pragma unroll
    for (int j = 0; j < 8; j++) {
        const int idx = tid + j * 256;
        const int plane = idx >> 9;
        const int rem = idx & 511;
        const int row = rem >> 2;
        const int c16 = rem & 3;
        const __nv_bfloat16* base;
        if (plane == 0)      base = g_Ahi + (size_t)(rowBase + row) * IN_DIM;
        else if (plane == 1) base = g_Alo + (size_t)(rowBase + row) * IN_DIM;
        else if (plane == 2) base = g_Whi + (size_t)(cb + row) * IN_DIM;
        else                 base = g_Wlo + (size_t)(cb + row) * IN_DIM;
        gptr[j] = base + c16 * 8;
        smoff[j] = plane * P2PLANE + row * P2PITCH + c16 * 16;
    }

#define P2LOAD(buf, k0) {                                                        \
    _Pragma("unroll") for (int j = 0; j < 8; j++) {                              \
        unsigned int sa = sdyn + (buf) * P2BUF + smoff[j];                       \
        asm volatile("cp.async.cg.shared.global [%0], [%1], 16;"                 \
                     :: "r"(sa), "l"(gptr[j] + (k0)));                           \
    }                                                                            \
    asm volatile("cp.async.commit_group;"); }

    float acc[2][8][4];
#pragma unroll
    for (int mt = 0; mt < 2; mt++)
#pragma unroll
        for (int nt = 0; nt < 8; nt++)
#pragma unroll
            for (int q = 0; q < 4; q++) acc[mt][nt][q] = 0.f;

    const int NST = IN_DIM / 32;
    P2LOAD(0, 0)
    P2LOAD(1, 32)

    for (int s = 0; s < NST; s++) {
        if (s < NST - 2) { asm volatile("cp.async.wait_group 1;"); }
        else             { asm volatile("cp.async.wait_group 0;"); }
        __syncthreads();
        tc_compute2(sdyn + (s & 1) * P2BUF, acc, aoffA2, aoffB2);
        __syncthreads();
        if (s + 2 < NST) { P2LOAD(s & 1, (s + 2) * 32) }
    }
#undef P2LOAD

#pragma unroll
    for (int mt = 0; mt < 2; mt++) {
#pragma unroll
        for (int nt = 0; nt < 8; nt++) {
            const int col = lc + warpN * 64 + nt * 8 + 2 * tig;
            const float b0 = bias[col], b1 = bias[col + 1];
            const int r0 = rowBase + warpM * 32 + mt * 16 + gid;
            float* c0 = C + (size_t)r0 * segN + col;
            c0[0] = acc[mt][nt][0] + b0;
            c0[1] = acc[mt][nt][1] + b1;
            float* c1 = C + (size_t)(r0 + 8) * segN + col;
            c1[0] = acc[mt][nt][2] + b0;
            c1[1] = acc[mt][nt][3] + b1;
        }
    }
}

// ====== MEGA level GEMM (R14 register-staged, verbatim) =======================
__global__ void __launch_bounds__(256, 2)
mega_tc(const int* __restrict__ lch, const int* __restrict__ rch,
        float* __restrict__ Gp, int sF, int mgF, int ksF, int rowsF, int tilesF,
        float* __restrict__ stage, int sB, int mgB, int ksB, int rowsB)
{
    __shared__ __align__(16) __nv_bfloat16 sm[2][4][128 * SPITCH];
    TC_PROLOG
    const int lrow = tid >> 1, lhalf = (tid & 1) << 3;
    const int smOff = lrow * SPITCH + lhalf;

    int bx = blockIdx.x;
    const bool isF = bx < tilesF;
    if (!isF) bx -= tilesF;
    const int colTiles = isF ? 24 : 20;
    const int rows = isF ? rowsF : rowsB;
    const int colBase = (bx % colTiles) * BN;
    const int rowBase = ((bx / colTiles) % rows) * BM;
    const int z = bx / (colTiles * rows);
    const int mg = isF ? mgF : mgB;
    const int KTOT = isF ? 1024 : 512;
    const int ks = isF ? ksF : ksB;
    const int chunk = KTOT / ks;
    const int kBase = z * chunk;

    int r0 = rowBase + lrow; if (r0 >= mg) r0 = mg - 1;
    const __nv_bfloat16 *paHi0, *paLo0, *paHi1, *paLo1;
    if (isF) {
        const int node = sF + r0;
        const int il = lch[node], ir = rch[node];
        paHi0 = g_hfw_hi + (size_t)il * H;
        paLo0 = g_hfw_lo + (size_t)il * H;
        paHi1 = g_hfw_hi + (size_t)ir * H - H;
        paLo1 = g_hfw_lo + (size_t)ir * H - H;
    } else {
        const int node = sB + r0;
        paHi0 = g_hbw_hi + (size_t)node * H;
        paLo0 = g_hbw_lo + (size_t)node * H;
        paHi1 = paHi0; paLo1 = paLo0;
    }
    const __nv_bfloat16* pbHi = (isF ? g_Wfw_hi : g_Wbw_hi) + (size_t)(colBase + lrow) * KTOT;
    const __nv_bfloat16* pbLo = (isF ? g_Wfw_lo : g_Wbw_lo) + (size_t)(colBase + lrow) * KTOT;

    float acc[2][8][4];
#pragma unroll
    for (int mt = 0; mt < 2; mt++)
#pragma unroll
        for (int nt = 0; nt < 8; nt++)
#pragma unroll
            for (int q = 0; q < 4; q++) acc[mt][nt][q] = 0.f;

    uint4 rAh, rAl, rBh, rBl;
#define MEGA_LOAD(kb) {                                                \
    const int k = (kb) + lhalf;                                        \
    const __nv_bfloat16* ph = (k < H) ? paHi0 : paHi1;                 \
    const __nv_bfloat16* pl = (k < H) ? paLo0 : paLo1;                 \
    rAh = *(const uint4*)(ph + k);                                     \
    rAl = *(const uint4*)(pl + k);                                     \
    rBh = *(const uint4*)(pbHi + k);                                   \
    rBl = *(const uint4*)(pbLo + k); }

    MEGA_LOAD(kBase)
    SM_STORE(0)
    __syncthreads();

    const int NSTAGE = chunk / 16;
    for (int s = 0; s < NSTAGE; s++) {
        const int buf = s & 1;
        if (s + 1 < NSTAGE) { MEGA_LOAD(kBase + (s + 1) * 16) }
        TC_COMPUTE_LDSM(buf)
        if (s + 1 < NSTAGE) {
            SM_STORE((s + 1) & 1)
            __syncthreads();
        }
    }
#undef MEGA_LOAD

    float* outp = isF ? Gp : stage;
    const int stride = isF ? G6 : G5;
#pragma unroll
    for (int mt = 0; mt < 2; mt++) {
#pragma unroll
        for (int nt = 0; nt < 8; nt++) {
            const int col = colBase + warpN * 64 + nt * 8 + 2 * tig;
            const int ro = rowBase + warpM * 32 + mt * 16 + gid;
            if (ro < mg) {
                float* p = outp + (size_t)(z * mg + ro) * stride + col;
                p[0] = acc[mt][nt][0]; p[1] = acc[mt][nt][1];
            }
            if (ro + 8 < mg) {
                float* p = outp + (size_t)(z * mg + ro + 8) * stride + col;
                p[0] = acc[mt][nt][2]; p[1] = acc[mt][nt][3];
            }
        }
    }
}

// ====== MEGA gates (writeA: layer-0 emits layer-2 proj input splits) ==========
__global__ void gates_mega(
    const float* __restrict__ Gp, const float* __restrict__ x2f,
    const float* __restrict__ pxf,
    const float* __restrict__ bl, const float* __restrict__ br,
    float* __restrict__ cbf,
    const int* __restrict__ lch, const int* __restrict__ rch,
    int sF, int mF, int mgF, int ksF,
    const float* __restrict__ stage, const float* __restrict__ x2b,
    const float* __restrict__ pxb, const float* __restrict__ bh,
    float* __restrict__ cbb,
    const int* __restrict__ par, int sB, int sPar, int mPar, int ksPar,
    float* __restrict__ dst, int writeA)
{
    const int col = threadIdx.x;
    int j = blockIdx.x;
    if (j < mF) {
        const int node = sF + j;
        float v[6];
        const float* xr = x2f + (size_t)node * G6;
#pragma unroll
        for (int g = 0; g < 6; g++) v[g] = xr[g * H + col] + bl[g * H + col] + br[g * H + col];
        if (j < mgF) {
            for (int z = 0; z < ksF; z++) {
                const float* gp = Gp + (size_t)(z * mgF + j) * G6;
#pragma unroll
                for (int g = 0; g < 6; g++) v[g] += gp[g * H + col];
            }
        }
        float iv = sigm(v[0]), ov = sigm(v[1]), fl = sigm(v[2]), fr = sigm(v[3]);
        float uv = tanhf(v[4]), rv = sigm(v[5]);
        float cl = cbf[(size_t)lch[node] * H + col];
        float cr = cbf[(size_t)rch[node] * H + col];
        float c = iv * uv + fl * cl + fr * cr;
        float hc = ov * tanhf(c);
        float hf = rv * hc + (1.f - rv) * pxf[(size_t)node * H + col];
        cbf[(size_t)node * H + col] = c;
        __nv_bfloat16 hh = __float2bfloat16(hf);
        __nv_bfloat16 ll = __float2bfloat16(hf - __bfloat162float(hh));
        g_hfw_hi[(size_t)node * H + col] = hh;
        g_hfw_lo[(size_t)node * H + col] = ll;
        if (writeA) {
            g_Ahi[(size_t)node * IN_DIM + col] = hh;
            g_Alo[(size_t)node * IN_DIM + col] = ll;
        } else {
            dst[(size_t)node * IN_DIM + col] = hf;
        }
    } else {
        j -= mF;
        const int node = sB + j;
        const float* xr = x2b + (size_t)node * G5;
        float v[5];
#pragma unroll
        for (int g = 0; g < 5; g++) v[g] = xr[g * H + col] + bh[g * H + col];
        if (sPar >= 0) {
            const int rp = par[node] - sPar;
            for (int z = 0; z < ksPar; z++) {
                const float* y = stage + (size_t)(z * mPar + rp) * G5;
#pragma unroll
                for (int g = 0; g < 5; g++) v[g] += y[g * H + col];
            }
        }
        float iv = sigm(v[0]), ov = sigm(v[1]), fv = sigm(v[2]);
        float uv = tanhf(v[3]), rv = sigm(v[4]);
        float cp = cbb[(size_t)par[node] * H + col];
        float c = iv * uv + fv * cp;
        float hc = ov * tanhf(c);
        float hf = rv * hc + (1.f - rv) * pxb[(size_t)node * H + col];
        cbb[(size_t)node * H + col] = c;
        __nv_bfloat16 hh = __float2bfloat16(hf);
        __nv_bfloat16 ll = __float2bfloat16(hf - __bfloat162float(hh));
        g_hbw_hi[(size_t)node * H + col] = hh;
        g_hbw_lo[(size_t)node * H + col] = ll;
        if (writeA) {
            g_Ahi[(size_t)node * IN_DIM + H + col] = hh;
            g_Alo[(size_t)node * IN_DIM + H + col] = ll;
        } else {
            dst[(size_t)node * IN_DIM + H + col] = hf;
        }
    }
}

static inline int ksel(int mg) {
    if (mg <= 32)  return 16;
    if (mg <= 128) return 8;
    if (mg <= 512) return 4;
    return 2;
}

// ------------------------------- launch ---------------------------------------
extern "C" void kernel_launch(void* const* d_in, const int* in_sizes, int n_in,
                              void* d_out, int out_size) {
    const float* features = (const float*)d_in[0];
    const float* fw_Wp = (const float*)d_in[1];
    const float* fw_bp = (const float*)d_in[2];
    const float* fw_Wx = (const float*)d_in[3];
    const float* fw_bx = (const float*)d_in[4];
    const float* fw_Wl = (const float*)d_in[5];
    const float* fw_bl = (const float*)d_in[6];
    const float* fw_Wr = (const float*)d_in[7];
    const float* fw_br = (const float*)d_in[8];
    const float* bw_Wp = (const float*)d_in[9];
    const float* bw_bp = (const float*)d_in[10];
    const float* bw_Wx = (const float*)d_in[11];
    const float* bw_bx = (const float*)d_in[12];
    const float* bw_Wh = (const float*)d_in[13];
    const float* bw_bh = (const float*)d_in[14];
    const int* left   = (const int*)d_in[17];
    const int* right  = (const int*)d_in[18];
    const int* parent = (const int*)d_in[19];
    float* out = (float*)d_out;

    float *px_fw, *x2_fw, *px_bw, *x2_bw, *c_fw, *c_bw, *Gs, *stg;
    cudaGetSymbolAddress((void**)&px_fw, g_px_fw);
    cudaGetSymbolAddress((void**)&x2_fw, g_x2_fw);
    cudaGetSymbolAddress((void**)&px_bw, g_px_bw);
    cudaGetSymbolAddress((void**)&x2_bw, g_x2_bw);
    cudaGetSymbolAddress((void**)&c_fw, g_c_fw);
    cudaGetSymbolAddress((void**)&c_bw, g_c_bw);
    cudaGetSymbolAddress((void**)&Gs, g_G);
    cudaGetSymbolAddress((void**)&stg, g_stage);

    cudaFuncSetAttribute(proj_tc2, cudaFuncAttributeMaxDynamicSharedMemorySize, P2SMEM);

    zero_slots_kernel<<<1, H>>>();

    static const int LSTART[NLEV] = {0, 1, 3, 7, 15, 31, 63, 127, 255, 511, 1023, 2047, 4095};
    static const int LSIZE[NLEV]  = {1, 2, 4, 8, 16, 32, 64, 128, 256, 512, 1024, 2048, 1};
    static const int MGV[NLEV]    = {1, 2, 4, 8, 16, 32, 64, 128, 256, 512, 1024, 1, 0};

    for (int l = 0; l < 2; l++) {
        const float* Wp_f = fw_Wp + (size_t)l * H * IN_DIM;
        const float* bp_f = fw_bp + (size_t)l * H;
        const float* Wx_f = fw_Wx + (size_t)l * G6 * IN_DIM;
        const float* bx_f = fw_bx + (size_t)l * G6;
        const float* Wl_  = fw_Wl + (size_t)l * G6 * H;
        const float* bl_  = fw_bl + (size_t)l * G6;
        const float* Wr_  = fw_Wr + (size_t)l * G6 * H;
        const float* br_  = fw_br + (size_t)l * G6;
        const float* Wp_b = bw_Wp + (size_t)l * H * IN_DIM;
        const float* bp_b = bw_bp + (size_t)l * H;
        const float* Wx_b = bw_Wx + (size_t)l * G5 * IN_DIM;
        const float* bx_b = bw_bx + (size_t)l * G5;
        const float* Wh_  = bw_Wh + (size_t)l * G5 * H;
        const float* bh_  = bw_bh + (size_t)l * G5;

        // layer 0: split A + all weights; layer 1: A comes pre-split from gates
        const int base = (l == 0) ? 0 : SS0;
        split_all<<<(SS7 - base + 255) / 256, 256>>>(features, Wp_f, Wx_f, Wp_b, Wx_b,
                                                     Wl_, Wr_, Wh_, base);

        proj_tc2<<<dim3(NW / BN, N_OBJ / BM), 256, P2SMEM>>>(
            bp_f, px_fw, bx_f, x2_fw, bp_b, px_bw, bx_b, x2_bw);

        for (int t = 0; t < NLEV; t++) {
            const int dF = NLEV - 1 - t;
            const int sF = LSTART[dF], mF = LSIZE[dF], mgF = MGV[dF];
            const int ksF = ksel(mgF > 0 ? mgF : 1);
            const int rowsF = (mgF + BM - 1) / BM;
            const int tilesF = (mgF > 0) ? 24 * rowsF * ksF : 0;

            const int sB = LSTART[t], mB = LSIZE[t];
            const int dY = t - 1;
            const int mgB = (t >= 1) ? MGV[dY] : 0;
            const int ksB = ksel(mgB > 0 ? mgB : 1);
            const int rowsB = (mgB + BM - 1) / BM;
            const int tilesB = (mgB > 0) ? 20 * rowsB * ksB : 0;

            if (tilesF + tilesB > 0)
                mega_tc<<<tilesF + tilesB, 256>>>(
                    left, right, Gs, sF, (mgF > 0 ? mgF : 1), ksF,
                    (rowsF > 0 ? rowsF : 1), tilesF,
                    stg, LSTART[dY >= 0 ? dY : 0], (mgB > 0 ? mgB : 1),
                    ksB, (rowsB > 0 ? rowsB : 1));

            gates_mega<<<mF + mB, H>>>(
                Gs, x2_fw, px_fw, bl_, br_, c_fw, left, right,
                sF, mF, mgF, ksF,
                stg, x2_bw, px_bw, bh_, c_bw, parent,
                sB, (t >= 1) ? LSTART[dY] : -1, (mgB > 0 ? mgB : 1), ksB,
                out, (l == 0) ? 1 : 0);
        }
    }
}

// round 17
// speedup vs baseline: 1.1201x; 1.0071x over previous
#include <cuda_runtime.h>
#include <math.h>
#include <stdint.h>
#include <cuda_bf16.h>

#define N_OBJ  4096
#define H      512
#define IN_DIM 1024
#define G6     3072
#define G5     2560
#define NW     6656
#define NLEV   13
#define BM 128
#define BN 128
#define SPITCH 24

// ---------------- scratch ------------------------------------------------------
__device__ float g_px_fw[N_OBJ * H];
__device__ float g_x2_fw[N_OBJ * G6];
__device__ float g_px_bw[N_OBJ * H];
__device__ float g_x2_bw[N_OBJ * G5];
__device__ float g_c_fw[(N_OBJ + 1) * H];
__device__ float g_c_bw[(N_OBJ + 1) * H];
__device__ float g_G[2048 * G6];
__device__ float g_stage[2048 * G5];
__device__ __nv_bfloat16 g_hfw_hi[(N_OBJ + 1) * H];
__device__ __nv_bfloat16 g_hfw_lo[(N_OBJ + 1) * H];
__device__ __nv_bfloat16 g_hbw_hi[(N_OBJ + 1) * H];
__device__ __nv_bfloat16 g_hbw_lo[(N_OBJ + 1) * H];
__device__ __nv_bfloat16 g_Ahi[N_OBJ * IN_DIM];
__device__ __nv_bfloat16 g_Alo[N_OBJ * IN_DIM];
__device__ __nv_bfloat16 g_Whi[NW * IN_DIM];
__device__ __nv_bfloat16 g_Wlo[NW * IN_DIM];
__device__ __nv_bfloat16 g_Wfw_hi[G6 * 1024];
__device__ __nv_bfloat16 g_Wfw_lo[G6 * 1024];
__device__ __nv_bfloat16 g_Wbw_hi[G5 * H];
__device__ __nv_bfloat16 g_Wbw_lo[G5 * H];

// fast gate math: EX2+RCP based, rel err ~1e-7 (invisible vs bf16x3 1e-5)
__device__ __forceinline__ float sigm(float x) {
    return __fdividef(1.f, 1.f + __expf(-x));
}
__device__ __forceinline__ float tanh_f(float x) {
    return __fdividef(2.f, 1.f + __expf(-2.f * x)) - 1.f;
}

__global__ void zero_slots_kernel() {
    int t = threadIdx.x;
    g_c_fw[N_OBJ * H + t] = 0.f;
    g_c_bw[N_OBJ * H + t] = 0.f;
    __nv_bfloat16 z = __float2bfloat16(0.f);
    g_hfw_hi[N_OBJ * H + t] = z; g_hfw_lo[N_OBJ * H + t] = z;
    g_hbw_hi[N_OBJ * H + t] = z; g_hbw_lo[N_OBJ * H + t] = z;
}

// ---------------- bf16 hi/lo split ---------------------------------------------
__device__ __forceinline__ void split4(float4 v, unsigned int& h01, unsigned int& h23,
                                       unsigned int& l01, unsigned int& l23) {
    float f[4] = {v.x, v.y, v.z, v.w};
    __nv_bfloat16 h[4], l[4];
#pragma unroll
    for (int k = 0; k < 4; k++) {
        h[k] = __float2bfloat16(f[k]);
        l[k] = __float2bfloat16(f[k] - __bfloat162float(h[k]));
    }
    h01 = (unsigned int)*(unsigned short*)&h[0] | ((unsigned int)*(unsigned short*)&h[1] << 16);
    h23 = (unsigned int)*(unsigned short*)&h[2] | ((unsigned int)*(unsigned short*)&h[3] << 16);
    l01 = (unsigned int)*(unsigned short*)&l[0] | ((unsigned int)*(unsigned short*)&l[1] << 16);
    l23 = (unsigned int)*(unsigned short*)&l[2] | ((unsigned int)*(unsigned short*)&l[3] << 16);
}

#define SS0 1048576
#define SS1 1179648
#define SS2 1966080
#define SS3 2097152
#define SS4 2752512
#define SS5 3145728
#define SS6 3538944
#define SS7 3866624
__global__ void split_all(const float* __restrict__ A,
                          const float* __restrict__ Wpf, const float* __restrict__ Wxf,
                          const float* __restrict__ Wpb, const float* __restrict__ Wxb,
                          const float* __restrict__ Wl, const float* __restrict__ Wr,
                          const float* __restrict__ Wh, int base) {
    long i = base + (long)blockIdx.x * blockDim.x + threadIdx.x;
    if (i >= SS7) return;
    unsigned int h01, h23, l01, l23;
    if (i < SS0) {
        split4(((const float4*)A)[i], h01, h23, l01, l23);
        ((uint2*)g_Ahi)[i] = make_uint2(h01, h23);
        ((uint2*)g_Alo)[i] = make_uint2(l01, l23);
    } else if (i < SS4) {
        const float* src; long j; long doff;
        if (i < SS1)      { src = Wpf; j = i - SS0; doff = 0; }
        else if (i < SS2) { src = Wxf; j = i - SS1; doff = 131072; }
        else if (i < SS3) { src = Wpb; j = i - SS2; doff = 917504; }
        else              { src = Wxb; j = i - SS3; doff = 1048576; }
        split4(((const float4*)src)[j], h01, h23, l01, l23);
        ((uint2*)g_Whi)[doff + j] = make_uint2(h01, h23);
        ((uint2*)g_Wlo)[doff + j] = make_uint2(l01, l23);
    } else if (i < SS6) {
        const float* src; long j; long coff;
        if (i < SS5) { src = Wl; j = i - SS4; coff = 0; }
        else         { src = Wr; j = i - SS5; coff = 128; }
        split4(((const float4*)src)[j], h01, h23, l01, l23);
        long row = j >> 7, c4 = j & 127;
        long d = row * 256 + coff + c4;
        ((uint2*)g_Wfw_hi)[d] = make_uint2(h01, h23);
        ((uint2*)g_Wfw_lo)[d] = make_uint2(l01, l23);
    } else {
        long j = i - SS6;
        split4(((const float4*)Wh)[j], h01, h23, l01, l23);
        ((uint2*)g_Wbw_hi)[j] = make_uint2(h01, h23);
        ((uint2*)g_Wbw_lo)[j] = make_uint2(l01, l23);
    }
}

// ================= mma.sync machinery ==========================================
#define MMA_BF16(acc, A, b0_, b1_)                                               \
    asm volatile("mma.sync.aligned.m16n8k16.row.col.f32.bf16.bf16.f32 "          \
                 "{%0,%1,%2,%3},{%4,%5,%6,%7},{%8,%9},{%0,%1,%2,%3};"            \
                 : "+f"(acc[0]), "+f"(acc[1]), "+f"(acc[2]), "+f"(acc[3])        \
                 : "r"(A[0]), "r"(A[1]), "r"(A[2]), "r"(A[3]), "r"(b0_), "r"(b1_))

#define LDSM4(r, addr)                                                           \
    asm volatile("ldmatrix.sync.aligned.m8n8.x4.shared.b16 {%0,%1,%2,%3}, [%4];" \
                 : "=r"((r)[0]), "=r"((r)[1]), "=r"((r)[2]), "=r"((r)[3])        \
                 : "r"(addr))

#define PLANE_B  (128 * SPITCH * 2)
#define BUF_B    (4 * PLANE_B)

#define TC_COMPUTE_LDSM(buf)                                                     \
    {                                                                            \
        const unsigned int b0a = smem_u32 + (buf) * BUF_B;                       \
        unsigned int ah[2][4], al[2][4];                                         \
        LDSM4(ah[0], b0a + aoffA);                                               \
        LDSM4(ah[1], b0a + aoffA + 768);                                         \
        LDSM4(al[0], b0a + PLANE_B + aoffA);                                     \
        LDSM4(al[1], b0a + PLANE_B + aoffA + 768);                               \
        _Pragma("unroll") for (int p = 0; p < 4; p++) {                          \
            unsigned int bh[4], bl[4];                                           \
            LDSM4(bh, b0a + 2 * PLANE_B + aoffB + p * 768);                      \
            LDSM4(bl, b0a + 3 * PLANE_B + aoffB + p * 768);                      \
            _Pragma("unroll") for (int mt = 0; mt < 2; mt++) {                   \
                MMA_BF16(acc[mt][2 * p],     ah[mt], bh[0], bh[1]);              \
                MMA_BF16(acc[mt][2 * p],     ah[mt], bl[0], bl[1]);              \
                MMA_BF16(acc[mt][2 * p],     al[mt], bh[0], bh[1]);              \
                MMA_BF16(acc[mt][2 * p + 1], ah[mt], bh[2], bh[3]);              \
                MMA_BF16(acc[mt][2 * p + 1], ah[mt], bl[2], bl[3]);              \
                MMA_BF16(acc[mt][2 * p + 1], al[mt], bh[2], bh[3]);              \
            }                                                                    \
        }                                                                        \
    }

#define TC_PROLOG                                                                \
    const int tid = threadIdx.x;                                                 \
    const int wid = tid >> 5, lane = tid & 31;                                   \
    const int gid = lane >> 2, tig = lane & 3;                                   \
    const int warpM = wid & 3, warpN = wid >> 2;                                 \
    const unsigned int smem_u32 = (unsigned int)__cvta_generic_to_shared(&sm[0][0][0]); \
    const unsigned int aoffA = ((warpM * 32 + (lane & 7) + ((lane >> 3) & 1) * 8) * SPITCH \
                                + (lane >> 4) * 8) * 2;                          \
    const unsigned int aoffB = ((warpN * 64 + (lane & 7) + (lane >> 4) * 8) * SPITCH \
                                + ((lane >> 3) & 1) * 8) * 2;

#define SM_STORE(b)                                                    \
    *(uint4*)&sm[b][0][smOff] = rAh;                                   \
    *(uint4*)&sm[b][1][smOff] = rAl;                                   \
    *(uint4*)&sm[b][2][smOff] = rBh;                                   \
    *(uint4*)&sm[b][3][smOff] = rBl;

// ========== projection v2: cp.async pipeline, K-stage 32 (R14 proven) =========
#define P2PITCH 80
#define P2PLANE (128 * P2PITCH)
#define P2BUF   (4 * P2PLANE)
#define P2SMEM  (2 * P2BUF)

__device__ __forceinline__ void tc_compute2(unsigned int base, float (&acc)[2][8][4],
                                            unsigned int aoffA2, unsigned int aoffB2) {
#pragma unroll
    for (int ksub = 0; ksub < 2; ksub++) {
        const unsigned int b0a = base + ksub * 32;
        unsigned int ah[2][4], al[2][4];
        LDSM4(ah[0], b0a + aoffA2);
        LDSM4(ah[1], b0a + aoffA2 + 1280);
        LDSM4(al[0], b0a + P2PLANE + aoffA2);
        LDSM4(al[1], b0a + P2PLANE + aoffA2 + 1280);
#pragma unroll
        for (int p = 0; p < 4; p++) {
            unsigned int bh[4], bl[4];
            LDSM4(bh, b0a + 2 * P2PLANE + aoffB2 + p * 1280);
            LDSM4(bl, b0a + 3 * P2PLANE + aoffB2 + p * 1280);
#pragma unroll
            for (int mt = 0; mt < 2; mt++) {
                MMA_BF16(acc[mt][2 * p],     ah[mt], bh[0], bh[1]);
                MMA_BF16(acc[mt][2 * p],     ah[mt], bl[0], bl[1]);
                MMA_BF16(acc[mt][2 * p],     al[mt], bh[0], bh[1]);
                MMA_BF16(acc[mt][2 * p + 1], ah[mt], bh[2], bh[3]);
                MMA_BF16(acc[mt][2 * p + 1], ah[mt], bl[2], bl[3]);
                MMA_BF16(acc[mt][2 * p + 1], al[mt], bh[2], bh[3]);
            }
        }
    }
}

__global__ void __launch_bounds__(256, 2)
proj_tc2(const float* __restrict__ bpf, float* __restrict__ pxf,
         const float* __restrict__ bxf, float* __restrict__ x2f,
         const float* __restrict__ bpb, float* __restrict__ pxb,
         const float* __restrict__ bxb, float* __restrict__ x2b)
{
    extern __shared__ __align__(16) char dynsm[];
    const int tid = threadIdx.x;
    const int wid = tid >> 5, lane = tid & 31;
    const int gid = lane >> 2, tig = lane & 3;
    const int warpM = wid & 3, warpN = wid >> 2;
    const unsigned int sdyn = (unsigned int)__cvta_generic_to_shared(dynsm);
    const unsigned int aoffA2 = (warpM * 32 + (lane & 7) + ((lane >> 3) & 1) * 8) * P2PITCH
                                + (lane >> 4) * 16;
    const unsigned int aoffB2 = (warpN * 64 + (lane & 7) + (lane >> 4) * 8) * P2PITCH
                                + ((lane >> 3) & 1) * 16;

    const int rowBase = blockIdx.y * BM;
    const int cb = blockIdx.x * BN;

    const float* bias; float* C; int segN, lc;
    if (cb < 512)       { bias = bpf; C = pxf; segN = 512; lc = cb; }
    else if (cb < 3584) { bias = bxf; C = x2f; segN = G6;  lc = cb - 512; }
    else if (cb < 4096) { bias = bpb; C = pxb; segN = 512; lc = cb - 3584; }
    else                { bias = bxb; C = x2b; segN = G5;  lc = cb - 4096; }

    const __nv_bfloat16* gptr[8];
    unsigned int smoff[8];
#pragma unroll
    for (int j = 0; j < 8; j++) {
        const int idx = tid + j * 256;
        const int plane = idx >> 9;
        const int rem = idx & 511;
        const int row = rem >> 2;
        const int c16 = rem & 3;
        const __nv_bfloat16* base;
        if (plane == 0)      base = g_Ahi + (size_t)(rowBase + row) * IN_DIM;
        else if (plane == 1) base = g_Alo + (size_t)(rowBase + row) * IN_DIM;
        else if (plane == 2) base = g_Whi + (size_t)(cb + row) * IN_DIM;
        else                 base = g_Wlo + (size_t)(cb + row) * IN_DIM;
        gptr[j] = base + c16 * 8;
        smoff[j] = plane * P2PLANE + row * P2PITCH + c16 * 16;
    }

#define P2LOAD(buf, k0) {                                                        \
    _Pragma("unroll") for (int j = 0; j < 8; j++) {                              \
        unsigned int sa = sdyn + (buf) * P2BUF + smoff[j];                       \
        asm volatile("cp.async.cg.shared.global [%0], [%1], 16;"                 \
                     :: "r"(sa), "l"(gptr[j] + (k0)));                           \
    }                                                                            \
    asm volatile("cp.async.commit_group;"); }

    float acc[2][8][4];
#pragma unroll
    for (int mt = 0; mt < 2; mt++)
#pragma unroll
        for (int nt = 0; nt < 8; nt++)
#pragma unroll
            for (int q = 0; q < 4; q++) acc[mt][nt][q] = 0.f;

    const int NST = IN_DIM / 32;
    P2LOAD(0, 0)
    P2LOAD(1, 32)

    for (int s = 0; s < NST; s++) {
        if (s < NST - 2) { asm volatile("cp.async.wait_group 1;"); }
        else             { asm volatile("cp.async.wait_group 0;"); }
        __syncthreads();
        tc_compute2(sdyn + (s & 1) * P2BUF, acc, aoffA2, aoffB2);
        __syncthreads();
        if (s + 2 < NST) { P2LOAD(s & 1, (s + 2) * 32) }
    }
#undef P2LOAD

#pragma unroll
    for (int mt = 0; mt < 2; mt++) {
#pragma unroll
        for (int nt = 0; nt < 8; nt++) {
            const int col = lc + warpN * 64 + nt * 8 + 2 * tig;
            const float b0 = bias[col], b1 = bias[col + 1];
            const int r0 = rowBase + warpM * 32 + mt * 16 + gid;
            float* c0 = C + (size_t)r0 * segN + col;
            c0[0] = acc[mt][nt][0] + b0;
            c0[1] = acc[mt][nt][1] + b1;
            float* c1 = C + (size_t)(r0 + 8) * segN + col;
            c1[0] = acc[mt][nt][2] + b0;
            c1[1] = acc[mt][nt][3] + b1;
        }
    }
}

// ====== MEGA level GEMM (R14 register-staged, verbatim) =======================
__global__ void __launch_bounds__(256, 2)
mega_tc(const int* __restrict__ lch, const int* __restrict__ rch,
        float* __restrict__ Gp, int sF, int mgF, int ksF, int rowsF, int tilesF,
        float* __restrict__ stage, int sB, int mgB, int ksB, int rowsB)
{
    __shared__ __align__(16) __nv_bfloat16 sm[2][4][128 * SPITCH];
    TC_PROLOG
    const int lrow = tid >> 1, lhalf = (tid & 1) << 3;
    const int smOff = lrow * SPITCH + lhalf;

    int bx = blockIdx.x;
    const bool isF = bx < tilesF;
    if (!isF) bx -= tilesF;
    const int colTiles = isF ? 24 : 20;
    const int rows = isF ? rowsF : rowsB;
    const int colBase = (bx % colTiles) * BN;
    const int rowBase = ((bx / colTiles) % rows) * BM;
    const int z = bx / (colTiles * rows);
    const int mg = isF ? mgF : mgB;
    const int KTOT = isF ? 1024 : 512;
    const int ks = isF ? ksF : ksB;
    const int chunk = KTOT / ks;
    const int kBase = z * chunk;

    int r0 = rowBase + lrow; if (r0 >= mg) r0 = mg - 1;
    const __nv_bfloat16 *paHi0, *paLo0, *paHi1, *paLo1;
    if (isF) {
        const int node = sF + r0;
        const int il = lch[node], ir = rch[node];
        paHi0 = g_hfw_hi + (size_t)il * H;
        paLo0 = g_hfw_lo + (size_t)il * H;
        paHi1 = g_hfw_hi + (size_t)ir * H - H;
        paLo1 = g_hfw_lo + (size_t)ir * H - H;
    } else {
        const int node = sB + r0;
        paHi0 = g_hbw_hi + (size_t)node * H;
        paLo0 = g_hbw_lo + (size_t)node * H;
        paHi1 = paHi0; paLo1 = paLo0;
    }
    const __nv_bfloat16* pbHi = (isF ? g_Wfw_hi : g_Wbw_hi) + (size_t)(colBase + lrow) * KTOT;
    const __nv_bfloat16* pbLo = (isF ? g_Wfw_lo : g_Wbw_lo) + (size_t)(colBase + lrow) * KTOT;

    float acc[2][8][4];
#pragma unroll
    for (int mt = 0; mt < 2; mt++)
#pragma unroll
        for (int nt = 0; nt < 8; nt++)
#pragma unroll
            for (int q = 0; q < 4; q++) acc[mt][nt][q] = 0.f;

    uint4 rAh, rAl, rBh, rBl;
#define MEGA_LOAD(kb) {                                                \
    const int k = (kb) + lhalf;                                        \
    const __nv_bfloat16* ph = (k < H) ? paHi0 : paHi1;                 \
    const __nv_bfloat16* pl = (k < H) ? paLo0 : paLo1;                 \
    rAh = *(const uint4*)(ph + k);                                     \
    rAl = *(const uint4*)(pl + k);                                     \
    rBh = *(const uint4*)(pbHi + k);                                   \
    rBl = *(const uint4*)(pbLo + k); }

    MEGA_LOAD(kBase)
    SM_STORE(0)
    __syncthreads();

    const int NSTAGE = chunk / 16;
    for (int s = 0; s < NSTAGE; s++) {
        const int buf = s & 1;
        if (s + 1 < NSTAGE) { MEGA_LOAD(kBase + (s + 1) * 16) }
        TC_COMPUTE_LDSM(buf)
        if (s + 1 < NSTAGE) {
            SM_STORE((s + 1) & 1)
            __syncthreads();
        }
    }
#undef MEGA_LOAD

    float* outp = isF ? Gp : stage;
    const int stride = isF ? G6 : G5;
#pragma unroll
    for (int mt = 0; mt < 2; mt++) {
#pragma unroll
        for (int nt = 0; nt < 8; nt++) {
            const int col = colBase + warpN * 64 + nt * 8 + 2 * tig;
            const int ro = rowBase + warpM * 32 + mt * 16 + gid;
            if (ro < mg) {
                float* p = outp + (size_t)(z * mg + ro) * stride + col;
                p[0] = acc[mt][nt][0]; p[1] = acc[mt][nt][1];
            }
            if (ro + 8 < mg) {
                float* p = outp + (size_t)(z * mg + ro + 8) * stride + col;
                p[0] = acc[mt][nt][2]; p[1] = acc[mt][nt][3];
            }
        }
    }
}

// ====== MEGA gates (fast math, writeA) ========================================
__global__ void gates_mega(
    const float* __restrict__ Gp, const float* __restrict__ x2f,
    const float* __restrict__ pxf,
    const float* __restrict__ bl, const float* __restrict__ br,
    float* __restrict__ cbf,
    const int* __restrict__ lch, const int* __restrict__ rch,
    int sF, int mF, int mgF, int ksF,
    const float* __restrict__ stage, const float* __restrict__ x2b,
    const float* __restrict__ pxb, const float* __restrict__ bh,
    float* __restrict__ cbb,
    const int* __restrict__ par, int sB, int sPar, int mPar, int ksPar,
    float* __restrict__ dst, int writeA)
{
    const int col = threadIdx.x;
    int j = blockIdx.x;
    if (j < mF) {
        const int node = sF + j;
        float v[6];
        const float* xr = x2f + (size_t)node * G6;
#pragma unroll
        for (int g = 0; g < 6; g++) v[g] = xr[g * H + col] + bl[g * H + col] + br[g * H + col];
        if (j < mgF) {
            for (int z = 0; z < ksF; z++) {
                const float* gp = Gp + (size_t)(z * mgF + j) * G6;
#pragma unroll
                for (int g = 0; g < 6; g++) v[g] += gp[g * H + col];
            }
        }
        float iv = sigm(v[0]), ov = sigm(v[1]), fl = sigm(v[2]), fr = sigm(v[3]);
        float uv = tanh_f(v[4]), rv = sigm(v[5]);
        float cl = cbf[(size_t)lch[node] * H + col];
        float cr = cbf[(size_t)rch[node] * H + col];
        float c = iv * uv + fl * cl + fr * cr;
        float hc = ov * tanh_f(c);
        float hf = rv * hc + (1.f - rv) * pxf[(size_t)node * H + col];
        cbf[(size_t)node * H + col] = c;
        __nv_bfloat16 hh = __float2bfloat16(hf);
        __nv_bfloat16 ll = __float2bfloat16(hf - __bfloat162float(hh));
        g_hfw_hi[(size_t)node * H + col] = hh;
        g_hfw_lo[(size_t)node * H + col] = ll;
        if (writeA) {
            g_Ahi[(size_t)node * IN_DIM + col] = hh;
            g_Alo[(size_t)node * IN_DIM + col] = ll;
        } else {
            dst[(size_t)node * IN_DIM + col] = hf;
        }
    } else {
        j -= mF;
        const int node = sB + j;
        const float* xr = x2b + (size_t)node * G5;
        float v[5];
#pragma unroll
        for (int g = 0; g < 5; g++) v[g] = xr[g * H + col] + bh[g * H + col];
        if (sPar >= 0) {
            const int rp = par[node] - sPar;
            for (int z = 0; z < ksPar; z++) {
                const float* y = stage + (size_t)(z * mPar + rp) * G5;
#pragma unroll
                for (int g = 0; g < 5; g++) v[g] += y[g * H + col];
            }
        }
        float iv = sigm(v[0]), ov = sigm(v[1]), fv = sigm(v[2]);
        float uv = tanh_f(v[3]), rv = sigm(v[4]);
        float cp = cbb[(size_t)par[node] * H + col];
        float c = iv * uv + fv * cp;
        float hc = ov * tanh_f(c);
        float hf = rv * hc + (1.f - rv) * pxb[(size_t)node * H + col];
        cbb[(size_t)node * H + col] = c;
        __nv_bfloat16 hh = __float2bfloat16(hf);
        __nv_bfloat16 ll = __float2bfloat16(hf - __bfloat162float(hh));
        g_hbw_hi[(size_t)node * H + col] = hh;
        g_hbw_lo[(size_t)node * H + col] = ll;
        if (writeA) {
            g_Ahi[(size_t)node * IN_DIM + H + col] = hh;
            g_Alo[(size_t)node * IN_DIM + H + col] = ll;
        } else {
            dst[(size_t)node * IN_DIM + H + col] = hf;
        }
    }
}

static inline int ksel(int mg) {
    if (mg <= 32)  return 16;
    if (mg <= 128) return 8;
    if (mg <= 512) return 4;
    return 2;
}

// ------------------------------- launch ---------------------------------------
extern "C" void kernel_launch(void* const* d_in, const int* in_sizes, int n_in,
                              void* d_out, int out_size) {
    const float* features = (const float*)d_in[0];
    const float* fw_Wp = (const float*)d_in[1];
    const float* fw_bp = (const float*)d_in[2];
    const float* fw_Wx = (const float*)d_in[3];
    const float* fw_bx = (const float*)d_in[4];
    const float* fw_Wl = (const float*)d_in[5];
    const float* fw_bl = (const float*)d_in[6];
    const float* fw_Wr = (const float*)d_in[7];
    const float* fw_br = (const float*)d_in[8];
    const float* bw_Wp = (const float*)d_in[9];
    const float* bw_bp = (const float*)d_in[10];
    const float* bw_Wx = (const float*)d_in[11];
    const float* bw_bx = (const float*)d_in[12];
    const float* bw_Wh = (const float*)d_in[13];
    const float* bw_bh = (const float*)d_in[14];
    const int* left   = (const int*)d_in[17];
    const int* right  = (const int*)d_in[18];
    const int* parent = (const int*)d_in[19];
    float* out = (float*)d_out;

    float *px_fw, *x2_fw, *px_bw, *x2_bw, *c_fw, *c_bw, *Gs, *stg;
    cudaGetSymbolAddress((void**)&px_fw, g_px_fw);
    cudaGetSymbolAddress((void**)&x2_fw, g_x2_fw);
    cudaGetSymbolAddress((void**)&px_bw, g_px_bw);
    cudaGetSymbolAddress((void**)&x2_bw, g_x2_bw);
    cudaGetSymbolAddress((void**)&c_fw, g_c_fw);
    cudaGetSymbolAddress((void**)&c_bw, g_c_bw);
    cudaGetSymbolAddress((void**)&Gs, g_G);
    cudaGetSymbolAddress((void**)&stg, g_stage);

    cudaFuncSetAttribute(proj_tc2, cudaFuncAttributeMaxDynamicSharedMemorySize, P2SMEM);

    zero_slots_kernel<<<1, H>>>();

    static const int LSTART[NLEV] = {0, 1, 3, 7, 15, 31, 63, 127, 255, 511, 1023, 2047, 4095};
    static const int LSIZE[NLEV]  = {1, 2, 4, 8, 16, 32, 64, 128, 256, 512, 1024, 2048, 1};
    static const int MGV[NLEV]    = {1, 2, 4, 8, 16, 32, 64, 128, 256, 512, 1024, 1, 0};

    for (int l = 0; l < 2; l++) {
        const float* Wp_f = fw_Wp + (size_t)l * H * IN_DIM;
        const float* bp_f = fw_bp + (size_t)l * H;
        const float* Wx_f = fw_Wx + (size_t)l * G6 * IN_DIM;
        const float* bx_f = fw_bx + (size_t)l * G6;
        const float* Wl_  = fw_Wl + (size_t)l * G6 * H;
        const float* bl_  = fw_bl + (size_t)l * G6;
        const float* Wr_  = fw_Wr + (size_t)l * G6 * H;
        const float* br_  = fw_br + (size_t)l * G6;
        const float* Wp_b = bw_Wp + (size_t)l * H * IN_DIM;
        const float* bp_b = bw_bp + (size_t)l * H;
        const float* Wx_b = bw_Wx + (size_t)l * G5 * IN_DIM;
        const float* bx_b = bw_bx + (size_t)l * G5;
        const float* Wh_  = bw_Wh + (size_t)l * G5 * H;
        const float* bh_  = bw_bh + (size_t)l * G5;

        const int base = (l == 0) ? 0 : SS0;
        split_all<<<(SS7 - base + 255) / 256, 256>>>(features, Wp_f, Wx_f, Wp_b, Wx_b,
                                                     Wl_, Wr_, Wh_, base);

        proj_tc2<<<dim3(NW / BN, N_OBJ / BM), 256, P2SMEM>>>(
            bp_f, px_fw, bx_f, x2_fw, bp_b, px_bw, bx_b, x2_bw);

        for (int t = 0; t < NLEV; t++) {
            const int dF = NLEV - 1 - t;
            const int sF = LSTART[dF], mF = LSIZE[dF], mgF = MGV[dF];
            const int ksF = ksel(mgF > 0 ? mgF : 1);
            const int rowsF = (mgF + BM - 1) / BM;
            const int tilesF = (mgF > 0) ? 24 * rowsF * ksF : 0;

            const int sB = LSTART[t], mB = LSIZE[t];
            const int dY = t - 1;
            const int mgB = (t >= 1) ? MGV[dY] : 0;
            const int ksB = ksel(mgB > 0 ? mgB : 1);
            const int rowsB = (mgB + BM - 1) / BM;
            const int tilesB = (mgB > 0) ? 20 * rowsB * ksB : 0;

            if (tilesF + tilesB > 0)
                mega_tc<<<tilesF + tilesB, 256>>>(
                    left, right, Gs, sF, (mgF > 0 ? mgF : 1), ksF,
                    (rowsF > 0 ? rowsF : 1), tilesF,
                    stg, LSTART[dY >= 0 ? dY : 0], (mgB > 0 ? mgB : 1),
                    ksB, (rowsB > 0 ? rowsB : 1));

            gates_mega<<<mF + mB, H>>>(
                Gs, x2_fw, px_fw, bl_, br_, c_fw, left, right,
                sF, mF, mgF, ksF,
                stg, x2_bw, px_bw, bh_, c_bw, parent,
                sB, (t >= 1) ? LSTART[dY] : -1, (mgB > 0 ? mgB : 1), ksB,
                out, (l == 0) ? 1 : 0);
        }
    }
}